// round 10
// baseline (speedup 1.0000x reference)
#include <cuda_runtime.h>
#include <cuda_fp16.h>
#include <math.h>
#include <stdint.h>

#define Bn   2
#define Sn   4096
#define Hn   1024
#define Mn   (Bn * Sn)       // 8192 rows
#define WIN  32

// ---------------- scratch (no allocations allowed) ----------------
// fp16 hi/lo pair buffers (u32 = two fp16, even k in low half)
__device__ uint32_t g_x_h  [Mn * Hn / 2],          g_x_l  [Mn * Hn / 2];
__device__ uint32_t g_wq_h [Hn * Hn / 2];
__device__ uint32_t g_wk_h [Hn * Hn / 2];
__device__ uint32_t g_wv_h [Hn * Hn / 2];
__device__ uint32_t g_wo_h [Hn * Hn / 2];
__device__ uint32_t g_w1_h [(Hn / 2) * Hn / 2];
__device__ uint32_t g_w2_h [Hn * (Hn / 2) / 2];
__device__ uint32_t g_at_h [Mn * Hn / 2],          g_at_l [Mn * Hn / 2];
__device__ uint32_t g_ln_h [Mn * Hn / 2],          g_ln_l [Mn * Hn / 2];
__device__ uint32_t g_h1_h [Mn * Hn / 4],          g_h1_l [Mn * Hn / 4];
__device__ float g_q   [Mn * Hn];
__device__ float g_k   [Mn * Hn];
__device__ float g_v   [Mn * Hn];
__device__ float g_drft[Mn * Hn];
__device__ float g_psc [4 * Mn * 32];
__device__ float g_prob[Mn * 32];

// ---------------- fp16 helpers ----------------
__device__ __forceinline__ uint32_t pack2_h(__half a, __half b) {
    __half2 t; t.x = a; t.y = b;
    return *(uint32_t*)&t;
}
__device__ __forceinline__ void split2h(float x, float y, uint32_t& h, uint32_t& l) {
    __half hx = __float2half_rn(x);
    __half hy = __float2half_rn(y);
    h = pack2_h(hx, hy);
    l = pack2_h(__float2half_rn(x - __half2float(hx)),
                __float2half_rn(y - __half2float(hy)));
}
__device__ __forceinline__ uint32_t hi2h(float x, float y) {
    return pack2_h(__float2half_rn(x), __float2half_rn(y));
}
// non-volatile: "+f" dependencies are enough; lets ptxas schedule freely
__device__ __forceinline__ void mma_f16(float c[4], const uint32_t a[4], uint32_t b0, uint32_t b1) {
    asm("mma.sync.aligned.m16n8k16.row.col.f32.f16.f16.f32 "
        "{%0,%1,%2,%3}, {%4,%5,%6,%7}, {%8,%9}, {%0,%1,%2,%3};\n"
        : "+f"(c[0]), "+f"(c[1]), "+f"(c[2]), "+f"(c[3])
        : "r"(a[0]), "r"(a[1]), "r"(a[2]), "r"(a[3]), "r"(b0), "r"(b1));
}
__device__ __forceinline__ void ldmx4(uint32_t r[4], const uint32_t* p) {
    uint32_t a = (uint32_t)__cvta_generic_to_shared(p);
    asm volatile("ldmatrix.sync.aligned.m8n8.x4.shared.b16 {%0,%1,%2,%3}, [%4];"
        : "=r"(r[0]), "=r"(r[1]), "=r"(r[2]), "=r"(r[3]) : "r"(a));
}
__device__ __forceinline__ void cp16(uint32_t sdst, const void* gsrc) {
    asm volatile("cp.async.cg.shared.global [%0], [%1], 16;" :: "r"(sdst), "l"(gsrc));
}
#define CP_COMMIT() asm volatile("cp.async.commit_group;" ::: "memory")

// ---------------- conversions ----------------
__global__ __launch_bounds__(256) void conv_pair(
    const float* __restrict__ in, uint32_t* __restrict__ hi, uint32_t* __restrict__ lo, int n4)
{
    int i = blockIdx.x * 256 + threadIdx.x;
    if (i >= n4) return;
    float4 v = ((const float4*)in)[i];
    uint32_t h0, l0, h1, l1;
    split2h(v.x, v.y, h0, l0);
    split2h(v.z, v.w, h1, l1);
    ((uint2*)hi)[i] = make_uint2(h0, h1);
    ((uint2*)lo)[i] = make_uint2(l0, l1);
}
__global__ __launch_bounds__(256) void conv_hi(
    const float* __restrict__ in, uint32_t* __restrict__ hi, int n4)
{
    int i = blockIdx.x * 256 + threadIdx.x;
    if (i >= n4) return;
    float4 v = ((const float4*)in)[i];
    ((uint2*)hi)[i] = make_uint2(hi2h(v.x, v.y), hi2h(v.z, v.w));
}

// ---------------- GEMM: C[M,N] = A[M,K] @ B[N,K]^T, 2-term fp16, cp.async pipelined ----------------
// A = Ah + Al (fp16 split); B = Bh (fp16). C = Ah*Bh + Al*Bh.
// EPI 0: fp32 plain     EPI 1: fp32 += aux1
// EPI 2: fp16-pair out = gelu(acc + aux2[n])    EPI 3: fp32 = aux1 + acc + aux2[n]
#define BM 128
#define BN 128
#define SLD 20                         // u32 row stride (16 used + 4 pad)
#define MATW (BM * SLD)                // u32 per matrix tile (2560)
#define STGW (3 * MATW)                // u32 per stage (Ah, Al, Bh)
#define GEMM_SMEM (2 * STGW * 4)       // bytes (61440)

template<int EPI>
__global__ __launch_bounds__(256, 2) void gemm_mma(
    const uint32_t* __restrict__ Ahg, const uint32_t* __restrict__ Alg,
    const uint32_t* __restrict__ Bhg,
    float* __restrict__ C, uint32_t* __restrict__ Chi, uint32_t* __restrict__ Clo,
    int M, int N, int K,
    const float* __restrict__ aux1, const float* __restrict__ aux2)
{
    extern __shared__ uint32_t smem[];

    const int Kd2  = K >> 1;
    const int nt   = Kd2 >> 4;          // k-tiles of 16 u32 (32 elements)
    const int tid  = threadIdx.x;
    const int wid  = tid >> 5;
    const int lane = tid & 31;
    const int g    = lane >> 2;
    const int tq   = lane & 3;

    const int bm = blockIdx.y * BM;
    const int bn = blockIdx.x * BN;
    const int m0 = (wid & 3) * 32;
    const int n0 = (wid >> 2) * 64;

    const int sr0 = tid >> 2,         sc0 = (tid & 3) << 2;
    const int sr1 = (tid + 256) >> 2, sc1 = ((tid + 256) & 3) << 2;
    const uint32_t smem_base = (uint32_t)__cvta_generic_to_shared(smem);

    float acc[2][8][4];
#pragma unroll
    for (int i = 0; i < 2; i++)
#pragma unroll
        for (int j = 0; j < 8; j++)
#pragma unroll
            for (int r = 0; r < 4; r++) acc[i][j][r] = 0.f;

    const int ar  = m0 + ((lane & 15) >> 3) * 8 + (lane & 7);
    const int ac4 = (lane >> 4) * 4;
    const int br  = n0 + (lane >> 4) * 8 + (lane & 7);
    const int bc4 = ((lane & 15) >> 3) * 4;

    auto stage = [&](int k, int b) {
        const uint32_t sbase = smem_base + (uint32_t)(b * STGW) * 4u;
        const int koff = k * 16;
        {
            const size_t ga = (size_t)(bm + sr0) * Kd2 + koff + sc0;
            const size_t gb = (size_t)(bn + sr0) * Kd2 + koff + sc0;
            const uint32_t so = (uint32_t)(sr0 * SLD + sc0) * 4u;
            cp16(sbase + 0 * MATW * 4 + so, Ahg + ga);
            cp16(sbase + 1 * MATW * 4 + so, Alg + ga);
            cp16(sbase + 2 * MATW * 4 + so, Bhg + gb);
        }
        {
            const size_t ga = (size_t)(bm + sr1) * Kd2 + koff + sc1;
            const size_t gb = (size_t)(bn + sr1) * Kd2 + koff + sc1;
            const uint32_t so = (uint32_t)(sr1 * SLD + sc1) * 4u;
            cp16(sbase + 0 * MATW * 4 + so, Ahg + ga);
            cp16(sbase + 1 * MATW * 4 + so, Alg + ga);
            cp16(sbase + 2 * MATW * 4 + so, Bhg + gb);
        }
    };

    stage(0, 0);
    CP_COMMIT();

    for (int k = 0; k < nt; k++) {
        const int b = k & 1;
        if (k + 1 < nt) {
            stage(k + 1, b ^ 1);
            CP_COMMIT();
            asm volatile("cp.async.wait_group 1;" ::: "memory");
        } else {
            asm volatile("cp.async.wait_group 0;" ::: "memory");
        }
        __syncthreads();

        const uint32_t* sAh = smem + b * STGW + 0 * MATW;
        const uint32_t* sAl = smem + b * STGW + 1 * MATW;
        const uint32_t* sBh = smem + b * STGW + 2 * MATW;

#pragma unroll
        for (int kc = 0; kc < 16; kc += 8) {
            uint32_t ah[2][4], al[2][4];
#pragma unroll
            for (int mf = 0; mf < 2; mf++) {
                ldmx4(ah[mf], sAh + (ar + mf * 16) * SLD + kc + ac4);
                ldmx4(al[mf], sAl + (ar + mf * 16) * SLD + kc + ac4);
            }
            // process p in halves: load B frags, then a burst of 8 hi-mmas
            // (all distinct accumulators), then 8 lo-mmas — no back-to-back RAW
#pragma unroll
            for (int h = 0; h < 2; h++) {
                uint32_t bh0[4], bh1[4];
                ldmx4(bh0, sBh + (br + (2 * h)     * 16) * SLD + kc + bc4);
                ldmx4(bh1, sBh + (br + (2 * h + 1) * 16) * SLD + kc + bc4);
                const int p0 = 4 * h, p1 = 4 * h + 2;
                // hi burst (8 mmas, 8 distinct accs)
                mma_f16(acc[0][p0],     ah[0], bh0[0], bh0[1]);
                mma_f16(acc[0][p0 + 1], ah[0], bh0[2], bh0[3]);
                mma_f16(acc[1][p0],     ah[1], bh0[0], bh0[1]);
                mma_f16(acc[1][p0 + 1], ah[1], bh0[2], bh0[3]);
                mma_f16(acc[0][p1],     ah[0], bh1[0], bh1[1]);
                mma_f16(acc[0][p1 + 1], ah[0], bh1[2], bh1[3]);
                mma_f16(acc[1][p1],     ah[1], bh1[0], bh1[1]);
                mma_f16(acc[1][p1 + 1], ah[1], bh1[2], bh1[3]);
                // lo burst (8 mmas, each >=8 issues after its hi partner)
                mma_f16(acc[0][p0],     al[0], bh0[0], bh0[1]);
                mma_f16(acc[0][p0 + 1], al[0], bh0[2], bh0[3]);
                mma_f16(acc[1][p0],     al[1], bh0[0], bh0[1]);
                mma_f16(acc[1][p0 + 1], al[1], bh0[2], bh0[3]);
                mma_f16(acc[0][p1],     al[0], bh1[0], bh1[1]);
                mma_f16(acc[0][p1 + 1], al[0], bh1[2], bh1[3]);
                mma_f16(acc[1][p1],     al[1], bh1[0], bh1[1]);
                mma_f16(acc[1][p1 + 1], al[1], bh1[2], bh1[3]);
            }
        }
        __syncthreads();
    }

    // ---- epilogue: frag (mf,nf) -> rows (g, g+8), cols nf*8 + tq*2 (+1) ----
#pragma unroll
    for (int mf = 0; mf < 2; mf++) {
#pragma unroll
        for (int nf = 0; nf < 8; nf++) {
            const int r0 = bm + m0 + mf * 16 + g;
            const int r1 = r0 + 8;
            const int cc = bn + n0 + nf * 8 + tq * 2;
            float v0 = acc[mf][nf][0], v1 = acc[mf][nf][1];
            float v2 = acc[mf][nf][2], v3 = acc[mf][nf][3];

            if (EPI == 1 || EPI == 3) {
                const float2 a0 = *(const float2*)(aux1 + (size_t)r0 * N + cc);
                const float2 a1 = *(const float2*)(aux1 + (size_t)r1 * N + cc);
                v0 += a0.x; v1 += a0.y; v2 += a1.x; v3 += a1.y;
            }
            if (EPI == 2 || EPI == 3) {
                const float2 bb = *(const float2*)(aux2 + cc);
                v0 += bb.x; v1 += bb.y; v2 += bb.x; v3 += bb.y;
            }
            if (EPI == 2) {
                v0 *= normcdff(v0); v1 *= normcdff(v1);
                v2 *= normcdff(v2); v3 *= normcdff(v3);
                uint32_t h, l;
                const int Nd2 = N >> 1;
                split2h(v0, v1, h, l);
                Chi[(size_t)r0 * Nd2 + (cc >> 1)] = h;
                Clo[(size_t)r0 * Nd2 + (cc >> 1)] = l;
                split2h(v2, v3, h, l);
                Chi[(size_t)r1 * Nd2 + (cc >> 1)] = h;
                Clo[(size_t)r1 * Nd2 + (cc >> 1)] = l;
            } else {
                *(float2*)(C + (size_t)r0 * N + cc) = make_float2(v0, v1);
                *(float2*)(C + (size_t)r1 * N + cc) = make_float2(v2, v3);
            }
        }
    }
}

// ---------------- attention: scores (H-split partials) ----------------
#define CH 64

__global__ __launch_bounds__(256) void attn_scores(
    const float* __restrict__ Q, const float* __restrict__ Kt, float* __restrict__ psc)
{
    __shared__ float Ks[63][CH + 1];
    __shared__ float Qs[32][CH + 1];

    const int tid = threadIdx.x;
    const int q0  = blockIdx.x * 32;
    const int b   = blockIdx.y;
    const int hs  = blockIdx.z;
    const int ti  = tid >> 3;
    const int wg  = tid & 7;

    float acc[4] = {0.f, 0.f, 0.f, 0.f};

    for (int h0 = hs * 256; h0 < hs * 256 + 256; h0 += CH) {
        for (int idx = tid; idx < 63 * (CH / 4); idx += 256) {
            int r  = idx / (CH / 4);
            int c  = (idx % (CH / 4)) * 4;
            int jb = q0 - 31 + r;
            float4 v = make_float4(0.f, 0.f, 0.f, 0.f);
            if (jb >= 0)
                v = *(const float4*)(Kt + (size_t)(b * Sn + jb) * Hn + h0 + c);
            Ks[r][c] = v.x; Ks[r][c + 1] = v.y; Ks[r][c + 2] = v.z; Ks[r][c + 3] = v.w;
        }
        for (int idx = tid; idx < 32 * (CH / 4); idx += 256) {
            int r = idx / (CH / 4);
            int c = (idx % (CH / 4)) * 4;
            float4 v = *(const float4*)(Q + (size_t)(b * Sn + q0 + r) * Hn + h0 + c);
            Qs[r][c] = v.x; Qs[r][c + 1] = v.y; Qs[r][c + 2] = v.z; Qs[r][c + 3] = v.w;
        }
        __syncthreads();
#pragma unroll 8
        for (int kk = 0; kk < CH; kk++) {
            float qv = Qs[ti][kk];
#pragma unroll
            for (int j = 0; j < 4; j++)
                acc[j] += qv * Ks[ti + wg * 4 + j][kk];
        }
        __syncthreads();
    }
    const size_t base = ((size_t)hs * Mn + b * Sn + q0 + ti) * 32 + wg * 4;
#pragma unroll
    for (int j = 0; j < 4; j++) psc[base + j] = acc[j];
}

// ---------------- attention: softmax ----------------
__global__ __launch_bounds__(256) void attn_softmax(
    const float* __restrict__ psc, float* __restrict__ prob)
{
    const int warp = threadIdx.x >> 5, lane = threadIdx.x & 31;
    const int row  = blockIdx.x * 8 + warp;
    const int iq   = row & (Sn - 1);
    int wmin = 31 - iq; if (wmin < 0) wmin = 0;

    float s = 0.f;
#pragma unroll
    for (int hs = 0; hs < 4; hs++)
        s += psc[((size_t)hs * Mn + row) * 32 + lane];
    s *= (1.0f / 32.0f);

    const bool valid = (lane >= wmin);
    float m = valid ? s : -1e30f;
#pragma unroll
    for (int o = 16; o; o >>= 1) m = fmaxf(m, __shfl_xor_sync(0xffffffffu, m, o));
    float p = valid ? expf(s - m) : 0.f;
    float sum = p;
#pragma unroll
    for (int o = 16; o; o >>= 1) sum += __shfl_xor_sync(0xffffffffu, sum, o);
    prob[(size_t)row * 32 + lane] = p / sum;
}

// ---------------- attention: PV, emits fp16 pairs ----------------
__global__ __launch_bounds__(256) void attn_pv(
    const float* __restrict__ V, const float* __restrict__ prob,
    uint32_t* __restrict__ Ohi, uint32_t* __restrict__ Olo)
{
    __shared__ float Vs[63][132];

    const int tid = threadIdx.x;
    const int q0  = blockIdx.x * 32;
    const int b   = blockIdx.y;
    const int h0  = blockIdx.z * 128;
    const int ti  = tid >> 3;
    const int hg  = tid & 7;

    for (int idx = tid; idx < 63 * 32; idx += 256) {
        int r  = idx >> 5;
        int c  = (idx & 31) << 2;
        int jb = q0 - 31 + r;
        float4 v = make_float4(0.f, 0.f, 0.f, 0.f);
        if (jb >= 0)
            v = *(const float4*)(V + (size_t)(b * Sn + jb) * Hn + h0 + c);
        Vs[r][c] = v.x; Vs[r][c + 1] = v.y; Vs[r][c + 2] = v.z; Vs[r][c + 3] = v.w;
    }
    float p[32];
    const float* pr = prob + (size_t)(b * Sn + q0 + ti) * 32;
#pragma unroll
    for (int w = 0; w < 32; w++) p[w] = pr[w];
    __syncthreads();

    float o[16];
#pragma unroll
    for (int c = 0; c < 16; c++) o[c] = 0.f;
#pragma unroll
    for (int w = 0; w < 32; w++) {
        const float pv = p[w];
        const float* vr = &Vs[ti + w][hg * 16];
#pragma unroll
        for (int c = 0; c < 16; c++) o[c] += pv * vr[c];
    }
    const size_t rowbase = (size_t)(b * Sn + q0 + ti) * (Hn / 2) + (h0 >> 1) + hg * 8;
#pragma unroll
    for (int c = 0; c < 16; c += 2) {
        uint32_t h, l;
        split2h(o[c], o[c + 1], h, l);
        Ohi[rowbase + (c >> 1)] = h;
        Olo[rowbase + (c >> 1)] = l;
    }
}

// ---------------- layernorm: fp32 in, fp16-pair out ----------------
__global__ __launch_bounds__(256) void ln_kernel(
    const float* __restrict__ X, const float* __restrict__ w,
    const float* __restrict__ bb, uint32_t* __restrict__ Yhi, uint32_t* __restrict__ Ylo)
{
    const int row = blockIdx.x;
    const float* x = X + (size_t)row * Hn;
    float s = 0.f, ss = 0.f;
    for (int i = threadIdx.x; i < Hn; i += 256) {
        float v = x[i]; s += v; ss += v * v;
    }
    __shared__ float red[64];
#pragma unroll
    for (int o = 16; o; o >>= 1) {
        s  += __shfl_down_sync(0xffffffffu, s,  o);
        ss += __shfl_down_sync(0xffffffffu, ss, o);
    }
    const int warp = threadIdx.x >> 5, lane = threadIdx.x & 31;
    if (lane == 0) { red[warp] = s; red[32 + warp] = ss; }
    __syncthreads();
    if (threadIdx.x == 0) {
        float S = 0.f, SS = 0.f;
        for (int i = 0; i < 8; i++) { S += red[i]; SS += red[32 + i]; }
        red[0] = S; red[1] = SS;
    }
    __syncthreads();
    const float mu   = red[0] * (1.0f / Hn);
    const float var  = red[1] * (1.0f / Hn) - mu * mu;
    const float rstd = rsqrtf(var + 1e-5f);

    for (int i = threadIdx.x; i < Hn / 2; i += 256) {
        float2 v  = ((const float2*)x)[i];
        float2 wv = ((const float2*)w)[i];
        float2 bv = ((const float2*)bb)[i];
        float y0 = (v.x - mu) * rstd * wv.x + bv.x;
        float y1 = (v.y - mu) * rstd * wv.y + bv.y;
        uint32_t h, l;
        split2h(y0, y1, h, l);
        Yhi[(size_t)row * (Hn / 2) + i] = h;
        Ylo[(size_t)row * (Hn / 2) + i] = l;
    }
}

// ---------------- launch ----------------
extern "C" void kernel_launch(void* const* d_in, const int* in_sizes, int n_in,
                              void* d_out, int out_size)
{
    const float* x   = (const float*)d_in[0];
    const float* Wq  = (const float*)d_in[1];
    const float* Wk  = (const float*)d_in[2];
    const float* Wv  = (const float*)d_in[3];
    const float* Wo  = (const float*)d_in[4];
    const float* lnw = (const float*)d_in[5];
    const float* lnb = (const float*)d_in[6];
    const float* W1  = (const float*)d_in[7];
    const float* b1  = (const float*)d_in[8];
    const float* W2  = (const float*)d_in[9];
    const float* b2  = (const float*)d_in[10];
    float* out = (float*)d_out;

    uint32_t *xh, *xl, *wqh, *wkh, *wvh, *woh, *w1h, *w2h;
    uint32_t *ath, *atl, *lnh, *lnl, *h1h, *h1l;
    float *q, *k, *v, *drft, *psc, *prob;
    cudaGetSymbolAddress((void**)&xh,  g_x_h);  cudaGetSymbolAddress((void**)&xl,  g_x_l);
    cudaGetSymbolAddress((void**)&wqh, g_wq_h);
    cudaGetSymbolAddress((void**)&wkh, g_wk_h);
    cudaGetSymbolAddress((void**)&wvh, g_wv_h);
    cudaGetSymbolAddress((void**)&woh, g_wo_h);
    cudaGetSymbolAddress((void**)&w1h, g_w1_h);
    cudaGetSymbolAddress((void**)&w2h, g_w2_h);
    cudaGetSymbolAddress((void**)&ath, g_at_h); cudaGetSymbolAddress((void**)&atl, g_at_l);
    cudaGetSymbolAddress((void**)&lnh, g_ln_h); cudaGetSymbolAddress((void**)&lnl, g_ln_l);
    cudaGetSymbolAddress((void**)&h1h, g_h1_h); cudaGetSymbolAddress((void**)&h1l, g_h1_l);
    cudaGetSymbolAddress((void**)&q,    g_q);
    cudaGetSymbolAddress((void**)&k,    g_k);
    cudaGetSymbolAddress((void**)&v,    g_v);
    cudaGetSymbolAddress((void**)&drft, g_drft);
    cudaGetSymbolAddress((void**)&psc,  g_psc);
    cudaGetSymbolAddress((void**)&prob, g_prob);

    cudaFuncSetAttribute(gemm_mma<0>, cudaFuncAttributeMaxDynamicSharedMemorySize, GEMM_SMEM);
    cudaFuncSetAttribute(gemm_mma<1>, cudaFuncAttributeMaxDynamicSharedMemorySize, GEMM_SMEM);
    cudaFuncSetAttribute(gemm_mma<2>, cudaFuncAttributeMaxDynamicSharedMemorySize, GEMM_SMEM);
    cudaFuncSetAttribute(gemm_mma<3>, cudaFuncAttributeMaxDynamicSharedMemorySize, GEMM_SMEM);

    // conversions: x -> hi/lo pairs; weights -> hi only
    conv_pair<<<(Mn * Hn / 4) / 256, 256>>>(x,  xh,  xl,  Mn * Hn / 4);
    conv_hi  <<<(Hn * Hn / 4) / 256, 256>>>(Wq, wqh, Hn * Hn / 4);
    conv_hi  <<<(Hn * Hn / 4) / 256, 256>>>(Wk, wkh, Hn * Hn / 4);
    conv_hi  <<<(Hn * Hn / 4) / 256, 256>>>(Wv, wvh, Hn * Hn / 4);
    conv_hi  <<<(Hn * Hn / 4) / 256, 256>>>(Wo, woh, Hn * Hn / 4);
    conv_hi  <<<(Hn * Hn / 8) / 256, 256>>>(W1, w1h, Hn * Hn / 8);
    conv_hi  <<<(Hn * Hn / 8) / 256, 256>>>(W2, w2h, Hn * Hn / 8);

    dim3 gridH (Hn / BN,       Mn / BM);   // (8, 64)
    dim3 gridH2((Hn / 2) / BN, Mn / BM);   // (4, 64)

    // q, k, v projections (fp32 out)
    gemm_mma<0><<<gridH, 256, GEMM_SMEM>>>(xh, xl, wqh, q, nullptr, nullptr, Mn, Hn, Hn, nullptr, nullptr);
    gemm_mma<0><<<gridH, 256, GEMM_SMEM>>>(xh, xl, wkh, k, nullptr, nullptr, Mn, Hn, Hn, nullptr, nullptr);
    gemm_mma<0><<<gridH, 256, GEMM_SMEM>>>(xh, xl, wvh, v, nullptr, nullptr, Mn, Hn, Hn, nullptr, nullptr);

    // banded attention
    attn_scores <<<dim3(Sn / 32, Bn, 4), 256>>>(q, k, psc);
    attn_softmax<<<Mn / 8, 256>>>(psc, prob);
    attn_pv     <<<dim3(Sn / 32, Bn, 8), 256>>>(v, prob, ath, atl);

    // draft = x + attn @ Wo^T  (fp32 out)
    gemm_mma<1><<<gridH, 256, GEMM_SMEM>>>(ath, atl, woh, drft, nullptr, nullptr, Mn, Hn, Hn, x, nullptr);

    // layernorm -> fp16 pairs
    ln_kernel<<<Mn, 256>>>(drft, lnw, lnb, lnh, lnl);

    // h1 = gelu(ln @ W1^T + b1) -> fp16 pairs
    gemm_mma<2><<<gridH2, 256, GEMM_SMEM>>>(lnh, lnl, w1h, nullptr, h1h, h1l, Mn, Hn / 2, Hn, nullptr, b1);

    // out = draft + h1 @ W2^T + b2  (fp32)
    gemm_mma<3><<<gridH, 256, GEMM_SMEM>>>(h1h, h1l, w2h, out, nullptr, nullptr, Mn, Hn, Hn / 2, drft, b2);
}

// round 11
// speedup vs baseline: 1.3891x; 1.3891x over previous
#include <cuda_runtime.h>
#include <cuda_fp16.h>
#include <math.h>
#include <stdint.h>

#define Bn   2
#define Sn   4096
#define Hn   1024
#define Mn   (Bn * Sn)       // 8192 rows
#define WIN  32

// ---------------- scratch (no allocations allowed) ----------------
// fp16 pair buffers (u32 = two fp16, even k in low half)
__device__ uint32_t g_x_h  [Mn * Hn / 2];
__device__ uint32_t g_wq_h [Hn * Hn / 2];
__device__ uint32_t g_wk_h [Hn * Hn / 2];
__device__ uint32_t g_wv_h [Hn * Hn / 2];
__device__ uint32_t g_wo_h [Hn * Hn / 2];
__device__ uint32_t g_w1_h [(Hn / 2) * Hn / 2];
__device__ uint32_t g_w2_h [Hn * (Hn / 2) / 2];
__device__ uint32_t g_at_h [Mn * Hn / 2];
__device__ uint32_t g_ln_h [Mn * Hn / 2];
__device__ uint32_t g_h1_h [Mn * Hn / 4];
__device__ float g_q   [Mn * Hn];
__device__ float g_k   [Mn * Hn];
__device__ float g_v   [Mn * Hn];
__device__ float g_drft[Mn * Hn];
__device__ float g_psc [4 * Mn * 32];
__device__ float g_prob[Mn * 32];

// ---------------- fp16 helpers ----------------
__device__ __forceinline__ uint32_t pack2_h(__half a, __half b) {
    __half2 t; t.x = a; t.y = b;
    return *(uint32_t*)&t;
}
__device__ __forceinline__ uint32_t hi2h(float x, float y) {
    return pack2_h(__float2half_rn(x), __float2half_rn(y));
}
__device__ __forceinline__ void mma_f16(float c[4], const uint32_t a[4], uint32_t b0, uint32_t b1) {
    asm("mma.sync.aligned.m16n8k16.row.col.f32.f16.f16.f32 "
        "{%0,%1,%2,%3}, {%4,%5,%6,%7}, {%8,%9}, {%0,%1,%2,%3};\n"
        : "+f"(c[0]), "+f"(c[1]), "+f"(c[2]), "+f"(c[3])
        : "r"(a[0]), "r"(a[1]), "r"(a[2]), "r"(a[3]), "r"(b0), "r"(b1));
}
__device__ __forceinline__ void ldmx4(uint32_t r[4], const uint32_t* p) {
    uint32_t a = (uint32_t)__cvta_generic_to_shared(p);
    asm volatile("ldmatrix.sync.aligned.m8n8.x4.shared.b16 {%0,%1,%2,%3}, [%4];"
        : "=r"(r[0]), "=r"(r[1]), "=r"(r[2]), "=r"(r[3]) : "r"(a));
}
__device__ __forceinline__ void cp16(uint32_t sdst, const void* gsrc) {
    asm volatile("cp.async.cg.shared.global [%0], [%1], 16;" :: "r"(sdst), "l"(gsrc));
}
#define CP_COMMIT() asm volatile("cp.async.commit_group;" ::: "memory")

// ---------------- conversion: fp32 -> fp16 pairs ----------------
__global__ __launch_bounds__(256) void conv_hi(
    const float* __restrict__ in, uint32_t* __restrict__ hi, int n4)
{
    int i = blockIdx.x * 256 + threadIdx.x;
    if (i >= n4) return;
    float4 v = ((const float4*)in)[i];
    ((uint2*)hi)[i] = make_uint2(hi2h(v.x, v.y), hi2h(v.z, v.w));
}

// ---------------- GEMM: C[M,N] = A[M,K] @ B[N,K]^T, fp16, 3-stage cp.async ----------------
// EPI 0: fp32 plain     EPI 1: fp32 += aux1
// EPI 2: fp16-pair out = gelu(acc + aux2[n])    EPI 3: fp32 = aux1 + acc + aux2[n]
#define BM 128
#define BN 128
#define SLD 20                         // u32 row stride (16 used + 4 pad)
#define MATW (BM * SLD)                // u32 per matrix tile (2560)
#define STGW (2 * MATW)                // u32 per stage (Ah, Bh)
#define NSTAGE 3
#define GEMM_SMEM (NSTAGE * STGW * 4)  // bytes (61440)

template<int EPI>
__global__ __launch_bounds__(256, 2) void gemm_mma(
    const uint32_t* __restrict__ Ahg, const uint32_t* __restrict__ Bhg,
    float* __restrict__ C, uint32_t* __restrict__ Chi,
    int M, int N, int K,
    const float* __restrict__ aux1, const float* __restrict__ aux2)
{
    extern __shared__ uint32_t smem[];

    const int Kd2  = K >> 1;
    const int nt   = Kd2 >> 4;          // k-tiles of 16 u32 (32 elements)
    const int tid  = threadIdx.x;
    const int wid  = tid >> 5;
    const int lane = tid & 31;
    const int g    = lane >> 2;
    const int tq   = lane & 3;

    const int bm = blockIdx.y * BM;
    const int bn = blockIdx.x * BN;
    const int m0 = (wid & 3) * 32;
    const int n0 = (wid >> 2) * 64;

    const int sr0 = tid >> 2,         sc0 = (tid & 3) << 2;
    const int sr1 = (tid + 256) >> 2, sc1 = ((tid + 256) & 3) << 2;
    const uint32_t smem_base = (uint32_t)__cvta_generic_to_shared(smem);

    float acc[2][8][4];
#pragma unroll
    for (int i = 0; i < 2; i++)
#pragma unroll
        for (int j = 0; j < 8; j++)
#pragma unroll
            for (int r = 0; r < 4; r++) acc[i][j][r] = 0.f;

    const int ar  = m0 + ((lane & 15) >> 3) * 8 + (lane & 7);
    const int ac4 = (lane >> 4) * 4;
    const int br  = n0 + (lane >> 4) * 8 + (lane & 7);
    const int bc4 = ((lane & 15) >> 3) * 4;

    auto stage = [&](int k, int b) {
        const uint32_t sbase = smem_base + (uint32_t)(b * STGW) * 4u;
        const int koff = k * 16;
        {
            const size_t ga = (size_t)(bm + sr0) * Kd2 + koff + sc0;
            const size_t gb = (size_t)(bn + sr0) * Kd2 + koff + sc0;
            const uint32_t so = (uint32_t)(sr0 * SLD + sc0) * 4u;
            cp16(sbase + 0 * MATW * 4 + so, Ahg + ga);
            cp16(sbase + 1 * MATW * 4 + so, Bhg + gb);
        }
        {
            const size_t ga = (size_t)(bm + sr1) * Kd2 + koff + sc1;
            const size_t gb = (size_t)(bn + sr1) * Kd2 + koff + sc1;
            const uint32_t so = (uint32_t)(sr1 * SLD + sc1) * 4u;
            cp16(sbase + 0 * MATW * 4 + so, Ahg + ga);
            cp16(sbase + 1 * MATW * 4 + so, Bhg + gb);
        }
    };

    stage(0, 0);
    CP_COMMIT();
    if (nt > 1) { stage(1, 1); CP_COMMIT(); }

    int b = 0;
    for (int k = 0; k < nt; k++) {
        if (k + 2 < nt) {
            int bs = b + 2; if (bs >= NSTAGE) bs -= NSTAGE;
            stage(k + 2, bs);
            CP_COMMIT();
            asm volatile("cp.async.wait_group 2;" ::: "memory");
        } else if (k + 1 < nt) {
            asm volatile("cp.async.wait_group 1;" ::: "memory");
        } else {
            asm volatile("cp.async.wait_group 0;" ::: "memory");
        }
        __syncthreads();

        const uint32_t* sAh = smem + b * STGW + 0 * MATW;
        const uint32_t* sBh = smem + b * STGW + 1 * MATW;

#pragma unroll
        for (int kc = 0; kc < 16; kc += 8) {
            uint32_t ah[2][4];
            ldmx4(ah[0], sAh + (ar     ) * SLD + kc + ac4);
            ldmx4(ah[1], sAh + (ar + 16) * SLD + kc + ac4);
#pragma unroll
            for (int h = 0; h < 2; h++) {
                uint32_t bh0[4], bh1[4];
                ldmx4(bh0, sBh + (br + (2 * h)     * 16) * SLD + kc + bc4);
                ldmx4(bh1, sBh + (br + (2 * h + 1) * 16) * SLD + kc + bc4);
                const int p0 = 4 * h, p1 = 4 * h + 2;
                mma_f16(acc[0][p0],     ah[0], bh0[0], bh0[1]);
                mma_f16(acc[0][p0 + 1], ah[0], bh0[2], bh0[3]);
                mma_f16(acc[1][p0],     ah[1], bh0[0], bh0[1]);
                mma_f16(acc[1][p0 + 1], ah[1], bh0[2], bh0[3]);
                mma_f16(acc[0][p1],     ah[0], bh1[0], bh1[1]);
                mma_f16(acc[0][p1 + 1], ah[0], bh1[2], bh1[3]);
                mma_f16(acc[1][p1],     ah[1], bh1[0], bh1[1]);
                mma_f16(acc[1][p1 + 1], ah[1], bh1[2], bh1[3]);
            }
        }
        __syncthreads();
        if (++b >= NSTAGE) b = 0;
    }

    // ---- epilogue: frag (mf,nf) -> rows (g, g+8), cols nf*8 + tq*2 (+1) ----
#pragma unroll
    for (int mf = 0; mf < 2; mf++) {
#pragma unroll
        for (int nf = 0; nf < 8; nf++) {
            const int r0 = bm + m0 + mf * 16 + g;
            const int r1 = r0 + 8;
            const int cc = bn + n0 + nf * 8 + tq * 2;
            float v0 = acc[mf][nf][0], v1 = acc[mf][nf][1];
            float v2 = acc[mf][nf][2], v3 = acc[mf][nf][3];

            if (EPI == 1 || EPI == 3) {
                const float2 a0 = *(const float2*)(aux1 + (size_t)r0 * N + cc);
                const float2 a1 = *(const float2*)(aux1 + (size_t)r1 * N + cc);
                v0 += a0.x; v1 += a0.y; v2 += a1.x; v3 += a1.y;
            }
            if (EPI == 2 || EPI == 3) {
                const float2 bb = *(const float2*)(aux2 + cc);
                v0 += bb.x; v1 += bb.y; v2 += bb.x; v3 += bb.y;
            }
            if (EPI == 2) {
                v0 *= normcdff(v0); v1 *= normcdff(v1);
                v2 *= normcdff(v2); v3 *= normcdff(v3);
                const int Nd2 = N >> 1;
                Chi[(size_t)r0 * Nd2 + (cc >> 1)] = hi2h(v0, v1);
                Chi[(size_t)r1 * Nd2 + (cc >> 1)] = hi2h(v2, v3);
            } else {
                *(float2*)(C + (size_t)r0 * N + cc) = make_float2(v0, v1);
                *(float2*)(C + (size_t)r1 * N + cc) = make_float2(v2, v3);
            }
        }
    }
}

// ---------------- attention: scores (H-split partials) ----------------
#define CH 64

__global__ __launch_bounds__(256) void attn_scores(
    const float* __restrict__ Q, const float* __restrict__ Kt, float* __restrict__ psc)
{
    __shared__ float Ks[63][CH + 1];
    __shared__ float Qs[32][CH + 1];

    const int tid = threadIdx.x;
    const int q0  = blockIdx.x * 32;
    const int b   = blockIdx.y;
    const int hs  = blockIdx.z;
    const int ti  = tid >> 3;
    const int wg  = tid & 7;

    float acc[4] = {0.f, 0.f, 0.f, 0.f};

    for (int h0 = hs * 256; h0 < hs * 256 + 256; h0 += CH) {
        for (int idx = tid; idx < 63 * (CH / 4); idx += 256) {
            int r  = idx / (CH / 4);
            int c  = (idx % (CH / 4)) * 4;
            int jb = q0 - 31 + r;
            float4 v = make_float4(0.f, 0.f, 0.f, 0.f);
            if (jb >= 0)
                v = *(const float4*)(Kt + (size_t)(b * Sn + jb) * Hn + h0 + c);
            Ks[r][c] = v.x; Ks[r][c + 1] = v.y; Ks[r][c + 2] = v.z; Ks[r][c + 3] = v.w;
        }
        for (int idx = tid; idx < 32 * (CH / 4); idx += 256) {
            int r = idx / (CH / 4);
            int c = (idx % (CH / 4)) * 4;
            float4 v = *(const float4*)(Q + (size_t)(b * Sn + q0 + r) * Hn + h0 + c);
            Qs[r][c] = v.x; Qs[r][c + 1] = v.y; Qs[r][c + 2] = v.z; Qs[r][c + 3] = v.w;
        }
        __syncthreads();
#pragma unroll 8
        for (int kk = 0; kk < CH; kk++) {
            float qv = Qs[ti][kk];
#pragma unroll
            for (int j = 0; j < 4; j++)
                acc[j] += qv * Ks[ti + wg * 4 + j][kk];
        }
        __syncthreads();
    }
    const size_t base = ((size_t)hs * Mn + b * Sn + q0 + ti) * 32 + wg * 4;
#pragma unroll
    for (int j = 0; j < 4; j++) psc[base + j] = acc[j];
}

// ---------------- attention: softmax ----------------
__global__ __launch_bounds__(256) void attn_softmax(
    const float* __restrict__ psc, float* __restrict__ prob)
{
    const int warp = threadIdx.x >> 5, lane = threadIdx.x & 31;
    const int row  = blockIdx.x * 8 + warp;
    const int iq   = row & (Sn - 1);
    int wmin = 31 - iq; if (wmin < 0) wmin = 0;

    float s = 0.f;
#pragma unroll
    for (int hs = 0; hs < 4; hs++)
        s += psc[((size_t)hs * Mn + row) * 32 + lane];
    s *= (1.0f / 32.0f);

    const bool valid = (lane >= wmin);
    float m = valid ? s : -1e30f;
#pragma unroll
    for (int o = 16; o; o >>= 1) m = fmaxf(m, __shfl_xor_sync(0xffffffffu, m, o));
    float p = valid ? expf(s - m) : 0.f;
    float sum = p;
#pragma unroll
    for (int o = 16; o; o >>= 1) sum += __shfl_xor_sync(0xffffffffu, sum, o);
    prob[(size_t)row * 32 + lane] = p / sum;
}

// ---------------- attention: PV, emits fp16 pairs ----------------
__global__ __launch_bounds__(256) void attn_pv(
    const float* __restrict__ V, const float* __restrict__ prob,
    uint32_t* __restrict__ Ohi)
{
    __shared__ float Vs[63][132];

    const int tid = threadIdx.x;
    const int q0  = blockIdx.x * 32;
    const int b   = blockIdx.y;
    const int h0  = blockIdx.z * 128;
    const int ti  = tid >> 3;
    const int hg  = tid & 7;

    for (int idx = tid; idx < 63 * 32; idx += 256) {
        int r  = idx >> 5;
        int c  = (idx & 31) << 2;
        int jb = q0 - 31 + r;
        float4 v = make_float4(0.f, 0.f, 0.f, 0.f);
        if (jb >= 0)
            v = *(const float4*)(V + (size_t)(b * Sn + jb) * Hn + h0 + c);
        Vs[r][c] = v.x; Vs[r][c + 1] = v.y; Vs[r][c + 2] = v.z; Vs[r][c + 3] = v.w;
    }
    float p[32];
    const float* pr = prob + (size_t)(b * Sn + q0 + ti) * 32;
#pragma unroll
    for (int w = 0; w < 32; w++) p[w] = pr[w];
    __syncthreads();

    float o[16];
#pragma unroll
    for (int c = 0; c < 16; c++) o[c] = 0.f;
#pragma unroll
    for (int w = 0; w < 32; w++) {
        const float pv = p[w];
        const float* vr = &Vs[ti + w][hg * 16];
#pragma unroll
        for (int c = 0; c < 16; c++) o[c] += pv * vr[c];
    }
    const size_t rowbase = (size_t)(b * Sn + q0 + ti) * (Hn / 2) + (h0 >> 1) + hg * 8;
#pragma unroll
    for (int c = 0; c < 16; c += 2)
        Ohi[rowbase + (c >> 1)] = hi2h(o[c], o[c + 1]);
}

// ---------------- layernorm: fp32 in, fp16-pair out ----------------
__global__ __launch_bounds__(256) void ln_kernel(
    const float* __restrict__ X, const float* __restrict__ w,
    const float* __restrict__ bb, uint32_t* __restrict__ Yhi)
{
    const int row = blockIdx.x;
    const float* x = X + (size_t)row * Hn;
    float s = 0.f, ss = 0.f;
    for (int i = threadIdx.x; i < Hn; i += 256) {
        float v = x[i]; s += v; ss += v * v;
    }
    __shared__ float red[64];
#pragma unroll
    for (int o = 16; o; o >>= 1) {
        s  += __shfl_down_sync(0xffffffffu, s,  o);
        ss += __shfl_down_sync(0xffffffffu, ss, o);
    }
    const int warp = threadIdx.x >> 5, lane = threadIdx.x & 31;
    if (lane == 0) { red[warp] = s; red[32 + warp] = ss; }
    __syncthreads();
    if (threadIdx.x == 0) {
        float S = 0.f, SS = 0.f;
        for (int i = 0; i < 8; i++) { S += red[i]; SS += red[32 + i]; }
        red[0] = S; red[1] = SS;
    }
    __syncthreads();
    const float mu   = red[0] * (1.0f / Hn);
    const float var  = red[1] * (1.0f / Hn) - mu * mu;
    const float rstd = rsqrtf(var + 1e-5f);

    for (int i = threadIdx.x; i < Hn / 2; i += 256) {
        float2 v  = ((const float2*)x)[i];
        float2 wv = ((const float2*)w)[i];
        float2 bv = ((const float2*)bb)[i];
        float y0 = (v.x - mu) * rstd * wv.x + bv.x;
        float y1 = (v.y - mu) * rstd * wv.y + bv.y;
        Yhi[(size_t)row * (Hn / 2) + i] = hi2h(y0, y1);
    }
}

// ---------------- launch ----------------
extern "C" void kernel_launch(void* const* d_in, const int* in_sizes, int n_in,
                              void* d_out, int out_size)
{
    const float* x   = (const float*)d_in[0];
    const float* Wq  = (const float*)d_in[1];
    const float* Wk  = (const float*)d_in[2];
    const float* Wv  = (const float*)d_in[3];
    const float* Wo  = (const float*)d_in[4];
    const float* lnw = (const float*)d_in[5];
    const float* lnb = (const float*)d_in[6];
    const float* W1  = (const float*)d_in[7];
    const float* b1  = (const float*)d_in[8];
    const float* W2  = (const float*)d_in[9];
    const float* b2  = (const float*)d_in[10];
    float* out = (float*)d_out;

    uint32_t *xh, *wqh, *wkh, *wvh, *woh, *w1h, *w2h, *ath, *lnh, *h1h;
    float *q, *k, *v, *drft, *psc, *prob;
    cudaGetSymbolAddress((void**)&xh,  g_x_h);
    cudaGetSymbolAddress((void**)&wqh, g_wq_h);
    cudaGetSymbolAddress((void**)&wkh, g_wk_h);
    cudaGetSymbolAddress((void**)&wvh, g_wv_h);
    cudaGetSymbolAddress((void**)&woh, g_wo_h);
    cudaGetSymbolAddress((void**)&w1h, g_w1_h);
    cudaGetSymbolAddress((void**)&w2h, g_w2_h);
    cudaGetSymbolAddress((void**)&ath, g_at_h);
    cudaGetSymbolAddress((void**)&lnh, g_ln_h);
    cudaGetSymbolAddress((void**)&h1h, g_h1_h);
    cudaGetSymbolAddress((void**)&q,    g_q);
    cudaGetSymbolAddress((void**)&k,    g_k);
    cudaGetSymbolAddress((void**)&v,    g_v);
    cudaGetSymbolAddress((void**)&drft, g_drft);
    cudaGetSymbolAddress((void**)&psc,  g_psc);
    cudaGetSymbolAddress((void**)&prob, g_prob);

    cudaFuncSetAttribute(gemm_mma<0>, cudaFuncAttributeMaxDynamicSharedMemorySize, GEMM_SMEM);
    cudaFuncSetAttribute(gemm_mma<1>, cudaFuncAttributeMaxDynamicSharedMemorySize, GEMM_SMEM);
    cudaFuncSetAttribute(gemm_mma<2>, cudaFuncAttributeMaxDynamicSharedMemorySize, GEMM_SMEM);
    cudaFuncSetAttribute(gemm_mma<3>, cudaFuncAttributeMaxDynamicSharedMemorySize, GEMM_SMEM);

    // conversions (fp16 pairs, once per tensor)
    conv_hi<<<(Mn * Hn / 4) / 256, 256>>>(x,  xh,  Mn * Hn / 4);
    conv_hi<<<(Hn * Hn / 4) / 256, 256>>>(Wq, wqh, Hn * Hn / 4);
    conv_hi<<<(Hn * Hn / 4) / 256, 256>>>(Wk, wkh, Hn * Hn / 4);
    conv_hi<<<(Hn * Hn / 4) / 256, 256>>>(Wv, wvh, Hn * Hn / 4);
    conv_hi<<<(Hn * Hn / 4) / 256, 256>>>(Wo, woh, Hn * Hn / 4);
    conv_hi<<<(Hn * Hn / 8) / 256, 256>>>(W1, w1h, Hn * Hn / 8);
    conv_hi<<<(Hn * Hn / 8) / 256, 256>>>(W2, w2h, Hn * Hn / 8);

    dim3 gridH (Hn / BN,       Mn / BM);   // (8, 64)
    dim3 gridH2((Hn / 2) / BN, Mn / BM);   // (4, 64)

    // q, k, v projections (fp32 out)
    gemm_mma<0><<<gridH, 256, GEMM_SMEM>>>(xh, wqh, q, nullptr, Mn, Hn, Hn, nullptr, nullptr);
    gemm_mma<0><<<gridH, 256, GEMM_SMEM>>>(xh, wkh, k, nullptr, Mn, Hn, Hn, nullptr, nullptr);
    gemm_mma<0><<<gridH, 256, GEMM_SMEM>>>(xh, wvh, v, nullptr, Mn, Hn, Hn, nullptr, nullptr);

    // banded attention
    attn_scores <<<dim3(Sn / 32, Bn, 4), 256>>>(q, k, psc);
    attn_softmax<<<Mn / 8, 256>>>(psc, prob);
    attn_pv     <<<dim3(Sn / 32, Bn, 8), 256>>>(v, prob, ath);

    // draft = x + attn @ Wo^T  (fp32 out)
    gemm_mma<1><<<gridH, 256, GEMM_SMEM>>>(ath, woh, drft, nullptr, Mn, Hn, Hn, x, nullptr);

    // layernorm -> fp16 pairs
    ln_kernel<<<Mn, 256>>>(drft, lnw, lnb, lnh);

    // h1 = gelu(ln @ W1^T + b1) -> fp16 pairs
    gemm_mma<2><<<gridH2, 256, GEMM_SMEM>>>(lnh, w1h, nullptr, h1h, Mn, Hn / 2, Hn, nullptr, b1);

    // out = draft + h1 @ W2^T + b2  (fp32)
    gemm_mma<3><<<gridH, 256, GEMM_SMEM>>>(h1h, w2h, out, nullptr, Mn, Hn, Hn / 2, drft, b2);
}